// round 4
// baseline (speedup 1.0000x reference)
#include <cuda_runtime.h>

// Problem constants (fixed by the dataset generator)
#define NN 50000          // nodes
#define NE 600000         // edges
#define CC 128            // channels
#define BM 64             // rows per tile
#define NT ((NN + BM - 1) / BM)   // 782 tiles
#define XSTR 68           // padded smem row stride (floats) for X^T / H^T

// dynamic smem: X^T (128 x 68) + H^T (128 x 68) + W1 (128x128) + W2 (128x128)
#define XS_OFF   0
#define HS_OFF   (128 * XSTR)
#define W1_OFF   (2 * 128 * XSTR)
#define W2_OFF   (2 * 128 * XSTR + 128 * 128)
#define SMEM_FLOATS (2 * 128 * XSTR + 2 * 128 * 128)
#define SMEM_BYTES  (SMEM_FLOATS * 4)   // 200704 B

// Scratch for the 3 hop-scaled MLP outputs (coef already folded in).
__device__ float g_G[3][(size_t)NN * CC];

// ---------- packed f32x2 helpers ----------
__device__ __forceinline__ unsigned long long dup2(float x) {
    unsigned long long r;
    asm("mov.b64 %0, {%1, %1};" : "=l"(r) : "r"(__float_as_uint(x)));
    return r;
}
__device__ __forceinline__ void fma2(unsigned long long& acc, unsigned long long a, unsigned long long b) {
    asm("fma.rn.f32x2 %0, %1, %2, %0;" : "+l"(acc) : "l"(a), "l"(b));
}
__device__ __forceinline__ float lo2(unsigned long long v) { return __uint_as_float((unsigned)v); }
__device__ __forceinline__ float hi2(unsigned long long v) { return __uint_as_float((unsigned)(v >> 32)); }

// One 64x128x128 GEMM micro-kernel: A^T in smem (k-major, stride XSTR),
// W in smem (k-major, row 128 floats). Thread (tm, tn) produces rows
// 8*tm..8*tm+7, cols 4*tn..4*tn+3 as 8x2 packed-f32x2 accumulators.
__device__ __forceinline__ void gemm_tile(const float* __restrict__ asrc,
                                          const float* __restrict__ wsrc,
                                          int tm, int tn,
                                          unsigned long long acc[8][2]) {
    #pragma unroll
    for (int i = 0; i < 8; ++i) { acc[i][0] = 0ull; acc[i][1] = 0ull; }
    const float* ap = asrc + tm * 8;
    const float* wp = wsrc + tn * 4;
    #pragma unroll 4
    for (int k = 0; k < CC; ++k) {
        float4 a0 = *(const float4*)(ap + k * XSTR);        // rows m..m+3 (broadcast in warp)
        float4 a1 = *(const float4*)(ap + k * XSTR + 4);    // rows m+4..m+7
        ulonglong2 bb = *(const ulonglong2*)(wp + k * CC);  // col pairs (n,n+1),(n+2,n+3)
        unsigned long long d;
        d = dup2(a0.x); fma2(acc[0][0], d, bb.x); fma2(acc[0][1], d, bb.y);
        d = dup2(a0.y); fma2(acc[1][0], d, bb.x); fma2(acc[1][1], d, bb.y);
        d = dup2(a0.z); fma2(acc[2][0], d, bb.x); fma2(acc[2][1], d, bb.y);
        d = dup2(a0.w); fma2(acc[3][0], d, bb.x); fma2(acc[3][1], d, bb.y);
        d = dup2(a1.x); fma2(acc[4][0], d, bb.x); fma2(acc[4][1], d, bb.y);
        d = dup2(a1.y); fma2(acc[5][0], d, bb.x); fma2(acc[5][1], d, bb.y);
        d = dup2(a1.z); fma2(acc[6][0], d, bb.x); fma2(acc[6][1], d, bb.y);
        d = dup2(a1.w); fma2(acc[7][0], d, bb.x); fma2(acc[7][1], d, bb.y);
    }
}

// Fused 2-layer MLP: out = scale * (relu(X@W1 + b1)@W2 + b2).
// blockIdx.y selects which of the 4 MLPs; persistent blocks loop over row tiles.
__global__ void __launch_bounds__(256, 1)
mlp_kernel(const float* __restrict__ emb,
           const float* __restrict__ loop_W1, const float* __restrict__ loop_b1,
           const float* __restrict__ loop_W2, const float* __restrict__ loop_b2,
           const float* __restrict__ rel_W1,  const float* __restrict__ rel_b1,
           const float* __restrict__ rel_W2,  const float* __restrict__ rel_b2,
           const float* __restrict__ hh_W1,   const float* __restrict__ hh_b1,
           const float* __restrict__ hh_W2,   const float* __restrict__ hh_b2,
           const float* __restrict__ hop_coef,
           float* __restrict__ d_out)
{
    extern __shared__ float smem[];
    float* xs  = smem + XS_OFF;
    float* hs  = smem + HS_OFF;
    float* ws1 = smem + W1_OFF;
    float* ws2 = smem + W2_OFF;

    const int which = blockIdx.y;
    const float *X, *W1, *b1, *W2, *b2;
    float* out;
    float scale = 1.0f;
    if (which == 0) {        // self/loop term -> base of output
        X = emb + 2ll * NN * CC;
        W1 = loop_W1; b1 = loop_b1; W2 = loop_W2; b2 = loop_b2;
        out = d_out;
    } else if (which == 1) { // hop 1 (rel MLP on x_t)
        X = emb + 2ll * NN * CC;
        W1 = rel_W1; b1 = rel_b1; W2 = rel_W2; b2 = rel_b2;
        out = g_G[0]; scale = __ldg(hop_coef + 0);
    } else if (which == 2) { // hop 2 (hh[0] on emb[t-1])
        X = emb + 1ll * NN * CC;
        W1 = hh_W1; b1 = hh_b1; W2 = hh_W2; b2 = hh_b2;
        out = g_G[1]; scale = __ldg(hop_coef + 1);
    } else {                 // hop 3 (hh[1] on emb[t-2])
        X = emb;
        W1 = hh_W1 + CC * CC; b1 = hh_b1 + CC; W2 = hh_W2 + CC * CC; b2 = hh_b2 + CC;
        out = g_G[2]; scale = __ldg(hop_coef + 2);
    }

    const int tid = threadIdx.x;
    const int tn = tid & 31;   // lane: columns 4*tn..4*tn+3
    const int tm = tid >> 5;   // warp: rows 8*tm..8*tm+7

    // Weights resident for the whole kernel (first __syncthreads covers this).
    for (int i = tid; i < CC * CC / 4; i += 256) {
        ((float4*)ws1)[i] = ((const float4*)W1)[i];
        ((float4*)ws2)[i] = ((const float4*)W2)[i];
    }
    const float4 b1v = *(const float4*)(b1 + 4 * tn);
    const float4 b2v = *(const float4*)(b2 + 4 * tn);

    for (int tile = blockIdx.x; tile < NT; tile += gridDim.x) {
        const int row0 = tile * BM;

        // Load X tile transposed into smem: xs[k*XSTR + m] = X[row0+m][k]
        #pragma unroll
        for (int it = 0; it < 8; ++it) {
            int f  = tid + it * 256;   // 0..2047 float4s
            int m  = f >> 5;           // 0..63
            int kq = f & 31;           // 0..31 (group of 4 k's)
            int r  = row0 + m;
            float4 v = (r < NN) ? *(const float4*)(X + (size_t)r * CC + 4 * kq)
                                : make_float4(0.f, 0.f, 0.f, 0.f);
            float* p = xs + (4 * kq) * XSTR + m;
            p[0] = v.x; p[XSTR] = v.y; p[2 * XSTR] = v.z; p[3 * XSTR] = v.w;
        }
        __syncthreads();

        // GEMM 1 + bias + relu, store H transposed for GEMM 2
        unsigned long long acc[8][2];
        gemm_tile(xs, ws1, tm, tn, acc);

        float f8[8][4];
        #pragma unroll
        for (int i = 0; i < 8; ++i) {
            f8[i][0] = fmaxf(lo2(acc[i][0]) + b1v.x, 0.f);
            f8[i][1] = fmaxf(hi2(acc[i][0]) + b1v.y, 0.f);
            f8[i][2] = fmaxf(lo2(acc[i][1]) + b1v.z, 0.f);
            f8[i][3] = fmaxf(hi2(acc[i][1]) + b1v.w, 0.f);
        }
        #pragma unroll
        for (int j = 0; j < 4; ++j) {
            float* q = hs + (4 * tn + j) * XSTR + tm * 8;
            *(float4*)q       = make_float4(f8[0][j], f8[1][j], f8[2][j], f8[3][j]);
            *(float4*)(q + 4) = make_float4(f8[4][j], f8[5][j], f8[6][j], f8[7][j]);
        }
        __syncthreads();

        // GEMM 2 + bias + scale, write to global
        gemm_tile(hs, ws2, tm, tn, acc);
        #pragma unroll
        for (int i = 0; i < 8; ++i) {
            int r = row0 + tm * 8 + i;
            if (r < NN) {
                float4 o;
                o.x = scale * (lo2(acc[i][0]) + b2v.x);
                o.y = scale * (hi2(acc[i][0]) + b2v.y);
                o.z = scale * (lo2(acc[i][1]) + b2v.z);
                o.w = scale * (hi2(acc[i][1]) + b2v.w);
                *(float4*)(out + (size_t)r * CC + 4 * tn) = o;
            }
        }
        // no sync needed here: next iteration's xs writes are safe (see barriers above)
    }
}

// One warp per edge: out[row] += G[w-1][col] (coef already folded into G).
// Vector red (16B) keeps L2 atomic-op count 4x lower than scalar atomicAdd.
__global__ void scatter_kernel(const int* __restrict__ ei,
                               const int* __restrict__ ew,
                               float* __restrict__ out)
{
    const int lane = threadIdx.x & 31;
    int gw = (blockIdx.x * blockDim.x + threadIdx.x) >> 5;
    const int nw = (gridDim.x * blockDim.x) >> 5;
    for (int e = gw; e < NE; e += nw) {
        int row = ei[e];
        int col = ei[NE + e];
        int w = ew[e] - 1;
        if ((unsigned)w > 2u) continue;   // defensive; weights are 1..3
        const float4 v = *(const float4*)(&g_G[w][(size_t)col * CC + 4 * lane]);
        float* dst = out + (size_t)row * CC + 4 * lane;
        asm volatile("red.global.add.v4.f32 [%0], {%1, %2, %3, %4};"
                     :: "l"(dst), "f"(v.x), "f"(v.y), "f"(v.z), "f"(v.w)
                     : "memory");
    }
}

extern "C" void kernel_launch(void* const* d_in, const int* in_sizes, int n_in,
                              void* d_out, int out_size) {
    // metadata order: t, node_embeddings, edge_index, edge_weights,
    // loop_W1,b1,W2,b2, rel_W1,b1,W2,b2, hh_W1, hh_b1, hh_W2, hh_b2, hop_coef
    const float* emb      = (const float*)d_in[1];
    const int*   ei       = (const int*)  d_in[2];
    const int*   ew       = (const int*)  d_in[3];
    const float* loop_W1  = (const float*)d_in[4];
    const float* loop_b1  = (const float*)d_in[5];
    const float* loop_W2  = (const float*)d_in[6];
    const float* loop_b2  = (const float*)d_in[7];
    const float* rel_W1   = (const float*)d_in[8];
    const float* rel_b1   = (const float*)d_in[9];
    const float* rel_W2   = (const float*)d_in[10];
    const float* rel_b2   = (const float*)d_in[11];
    const float* hh_W1    = (const float*)d_in[12];
    const float* hh_b1    = (const float*)d_in[13];
    const float* hh_W2    = (const float*)d_in[14];
    const float* hh_b2    = (const float*)d_in[15];
    const float* hop_coef = (const float*)d_in[16];
    float* out = (float*)d_out;

    cudaFuncSetAttribute(mlp_kernel, cudaFuncAttributeMaxDynamicSharedMemorySize, SMEM_BYTES);

    // 152 persistent CTAs (1/SM on GB300), 4 MLP variants; writes d_out base + 3 hop scratches
    mlp_kernel<<<dim3(38, 4), 256, SMEM_BYTES>>>(
        emb, loop_W1, loop_b1, loop_W2, loop_b2,
        rel_W1, rel_b1, rel_W2, rel_b2,
        hh_W1, hh_b1, hh_W2, hh_b2, hop_coef, out);

    // edge scatter-add (depends on mlp_kernel; same stream ordering)
    scatter_kernel<<<1216, 256>>>(ei, ew, out);
}

// round 5
// speedup vs baseline: 1.0069x; 1.0069x over previous
#include <cuda_runtime.h>

// Problem constants (fixed by the dataset generator)
#define NN 50000          // nodes
#define NE 600000         // edges
#define CC 128            // channels
#define BM 64             // rows per tile
#define NT ((NN + BM - 1) / BM)   // 782 tiles
#define XSTR 68           // padded smem row stride (floats) for X^T / H^T

// dynamic smem: X^T (128 x 68) + H^T (128 x 68) + W1 (128x128) + W2 (128x128)
#define XS_OFF   0
#define HS_OFF   (128 * XSTR)
#define W1_OFF   (2 * 128 * XSTR)
#define W2_OFF   (2 * 128 * XSTR + 128 * 128)
#define SMEM_FLOATS (2 * 128 * XSTR + 2 * 128 * 128)
#define SMEM_BYTES  (SMEM_FLOATS * 4)   // 200704 B

// Scratch for the 3 hop-scaled MLP outputs (coef already folded in).
__device__ float g_G[3][(size_t)NN * CC];

// ---------- packed f32x2 helpers ----------
__device__ __forceinline__ unsigned long long dup2(float x) {
    unsigned long long r;
    asm("mov.b64 %0, {%1, %1};" : "=l"(r) : "r"(__float_as_uint(x)));
    return r;
}
__device__ __forceinline__ void fma2(unsigned long long& acc, unsigned long long a, unsigned long long b) {
    asm("fma.rn.f32x2 %0, %1, %2, %0;" : "+l"(acc) : "l"(a), "l"(b));
}
__device__ __forceinline__ float lo2(unsigned long long v) { return __uint_as_float((unsigned)v); }
__device__ __forceinline__ float hi2(unsigned long long v) { return __uint_as_float((unsigned)(v >> 32)); }

// One 64x128x128 GEMM micro-kernel: A^T in smem (k-major, stride XSTR),
// W in smem (k-major, row 128 floats). Thread (tm, tn) produces rows
// 8*tm..8*tm+7, cols 4*tn..4*tn+3 as 8x2 packed-f32x2 accumulators.
__device__ __forceinline__ void gemm_tile(const float* __restrict__ asrc,
                                          const float* __restrict__ wsrc,
                                          int tm, int tn,
                                          unsigned long long acc[8][2]) {
    #pragma unroll
    for (int i = 0; i < 8; ++i) { acc[i][0] = 0ull; acc[i][1] = 0ull; }
    const float* ap = asrc + tm * 8;
    const float* wp = wsrc + tn * 4;
    #pragma unroll 4
    for (int k = 0; k < CC; ++k) {
        float4 a0 = *(const float4*)(ap + k * XSTR);        // rows m..m+3 (broadcast in warp)
        float4 a1 = *(const float4*)(ap + k * XSTR + 4);    // rows m+4..m+7
        ulonglong2 bb = *(const ulonglong2*)(wp + k * CC);  // col pairs (n,n+1),(n+2,n+3)
        unsigned long long d;
        d = dup2(a0.x); fma2(acc[0][0], d, bb.x); fma2(acc[0][1], d, bb.y);
        d = dup2(a0.y); fma2(acc[1][0], d, bb.x); fma2(acc[1][1], d, bb.y);
        d = dup2(a0.z); fma2(acc[2][0], d, bb.x); fma2(acc[2][1], d, bb.y);
        d = dup2(a0.w); fma2(acc[3][0], d, bb.x); fma2(acc[3][1], d, bb.y);
        d = dup2(a1.x); fma2(acc[4][0], d, bb.x); fma2(acc[4][1], d, bb.y);
        d = dup2(a1.y); fma2(acc[5][0], d, bb.x); fma2(acc[5][1], d, bb.y);
        d = dup2(a1.z); fma2(acc[6][0], d, bb.x); fma2(acc[6][1], d, bb.y);
        d = dup2(a1.w); fma2(acc[7][0], d, bb.x); fma2(acc[7][1], d, bb.y);
    }
}

// Fused 2-layer MLP: out = scale * (relu(X@W1 + b1)@W2 + b2).
// blockIdx.y selects which of the 4 MLPs; persistent blocks loop over row tiles.
__global__ void __launch_bounds__(256, 1)
mlp_kernel(const float* __restrict__ emb,
           const float* __restrict__ loop_W1, const float* __restrict__ loop_b1,
           const float* __restrict__ loop_W2, const float* __restrict__ loop_b2,
           const float* __restrict__ rel_W1,  const float* __restrict__ rel_b1,
           const float* __restrict__ rel_W2,  const float* __restrict__ rel_b2,
           const float* __restrict__ hh_W1,   const float* __restrict__ hh_b1,
           const float* __restrict__ hh_W2,   const float* __restrict__ hh_b2,
           const float* __restrict__ hop_coef,
           float* __restrict__ d_out)
{
    extern __shared__ float smem[];
    float* xs  = smem + XS_OFF;
    float* hs  = smem + HS_OFF;
    float* ws1 = smem + W1_OFF;
    float* ws2 = smem + W2_OFF;

    const int which = blockIdx.y;
    const float *X, *W1, *b1, *W2, *b2;
    float* out;
    float scale = 1.0f;
    if (which == 0) {        // self/loop term -> base of output
        X = emb + 2ll * NN * CC;
        W1 = loop_W1; b1 = loop_b1; W2 = loop_W2; b2 = loop_b2;
        out = d_out;
    } else if (which == 1) { // hop 1 (rel MLP on x_t)
        X = emb + 2ll * NN * CC;
        W1 = rel_W1; b1 = rel_b1; W2 = rel_W2; b2 = rel_b2;
        out = g_G[0]; scale = __ldg(hop_coef + 0);
    } else if (which == 2) { // hop 2 (hh[0] on emb[t-1])
        X = emb + 1ll * NN * CC;
        W1 = hh_W1; b1 = hh_b1; W2 = hh_W2; b2 = hh_b2;
        out = g_G[1]; scale = __ldg(hop_coef + 1);
    } else {                 // hop 3 (hh[1] on emb[t-2])
        X = emb;
        W1 = hh_W1 + CC * CC; b1 = hh_b1 + CC; W2 = hh_W2 + CC * CC; b2 = hh_b2 + CC;
        out = g_G[2]; scale = __ldg(hop_coef + 2);
    }

    const int tid = threadIdx.x;
    const int tn = tid & 31;   // lane: columns 4*tn..4*tn+3
    const int tm = tid >> 5;   // warp: rows 8*tm..8*tm+7

    // Weights resident for the whole kernel (first __syncthreads covers this).
    for (int i = tid; i < CC * CC / 4; i += 256) {
        ((float4*)ws1)[i] = ((const float4*)W1)[i];
        ((float4*)ws2)[i] = ((const float4*)W2)[i];
    }
    const float4 b1v = *(const float4*)(b1 + 4 * tn);
    const float4 b2v = *(const float4*)(b2 + 4 * tn);

    for (int tile = blockIdx.x; tile < NT; tile += gridDim.x) {
        const int row0 = tile * BM;

        // Load X tile transposed into smem: xs[k*XSTR + m] = X[row0+m][k]
        #pragma unroll
        for (int it = 0; it < 8; ++it) {
            int f  = tid + it * 256;   // 0..2047 float4s
            int m  = f >> 5;           // 0..63
            int kq = f & 31;           // 0..31 (group of 4 k's)
            int r  = row0 + m;
            float4 v = (r < NN) ? *(const float4*)(X + (size_t)r * CC + 4 * kq)
                                : make_float4(0.f, 0.f, 0.f, 0.f);
            float* p = xs + (4 * kq) * XSTR + m;
            p[0] = v.x; p[XSTR] = v.y; p[2 * XSTR] = v.z; p[3 * XSTR] = v.w;
        }
        __syncthreads();

        // GEMM 1 + bias + relu, store H transposed for GEMM 2
        unsigned long long acc[8][2];
        gemm_tile(xs, ws1, tm, tn, acc);

        float f8[8][4];
        #pragma unroll
        for (int i = 0; i < 8; ++i) {
            f8[i][0] = fmaxf(lo2(acc[i][0]) + b1v.x, 0.f);
            f8[i][1] = fmaxf(hi2(acc[i][0]) + b1v.y, 0.f);
            f8[i][2] = fmaxf(lo2(acc[i][1]) + b1v.z, 0.f);
            f8[i][3] = fmaxf(hi2(acc[i][1]) + b1v.w, 0.f);
        }
        #pragma unroll
        for (int j = 0; j < 4; ++j) {
            float* q = hs + (4 * tn + j) * XSTR + tm * 8;
            *(float4*)q       = make_float4(f8[0][j], f8[1][j], f8[2][j], f8[3][j]);
            *(float4*)(q + 4) = make_float4(f8[4][j], f8[5][j], f8[6][j], f8[7][j]);
        }
        __syncthreads();

        // GEMM 2 + bias + scale, write to global
        gemm_tile(hs, ws2, tm, tn, acc);
        #pragma unroll
        for (int i = 0; i < 8; ++i) {
            int r = row0 + tm * 8 + i;
            if (r < NN) {
                float4 o;
                o.x = scale * (lo2(acc[i][0]) + b2v.x);
                o.y = scale * (hi2(acc[i][0]) + b2v.y);
                o.z = scale * (lo2(acc[i][1]) + b2v.z);
                o.w = scale * (hi2(acc[i][1]) + b2v.w);
                *(float4*)(out + (size_t)r * CC + 4 * tn) = o;
            }
        }
        // no sync needed here: next iteration's xs writes are safe (see barriers above)
    }
}

// One warp per edge: out[row] += G[w-1][col] (coef already folded into G).
// Vector red (16B) keeps L2 atomic-op count 4x lower than scalar atomicAdd.
__global__ void scatter_kernel(const int* __restrict__ ei,
                               const int* __restrict__ ew,
                               float* __restrict__ out)
{
    const int lane = threadIdx.x & 31;
    int gw = (blockIdx.x * blockDim.x + threadIdx.x) >> 5;
    const int nw = (gridDim.x * blockDim.x) >> 5;
    for (int e = gw; e < NE; e += nw) {
        int row = ei[e];
        int col = ei[NE + e];
        int w = ew[e] - 1;
        if ((unsigned)w > 2u) continue;   // defensive; weights are 1..3
        const float4 v = *(const float4*)(&g_G[w][(size_t)col * CC + 4 * lane]);
        float* dst = out + (size_t)row * CC + 4 * lane;
        asm volatile("red.global.add.v4.f32 [%0], {%1, %2, %3, %4};"
                     :: "l"(dst), "f"(v.x), "f"(v.y), "f"(v.z), "f"(v.w)
                     : "memory");
    }
}

extern "C" void kernel_launch(void* const* d_in, const int* in_sizes, int n_in,
                              void* d_out, int out_size) {
    // metadata order: t, node_embeddings, edge_index, edge_weights,
    // loop_W1,b1,W2,b2, rel_W1,b1,W2,b2, hh_W1, hh_b1, hh_W2, hh_b2, hop_coef
    const float* emb      = (const float*)d_in[1];
    const int*   ei       = (const int*)  d_in[2];
    const int*   ew       = (const int*)  d_in[3];
    const float* loop_W1  = (const float*)d_in[4];
    const float* loop_b1  = (const float*)d_in[5];
    const float* loop_W2  = (const float*)d_in[6];
    const float* loop_b2  = (const float*)d_in[7];
    const float* rel_W1   = (const float*)d_in[8];
    const float* rel_b1   = (const float*)d_in[9];
    const float* rel_W2   = (const float*)d_in[10];
    const float* rel_b2   = (const float*)d_in[11];
    const float* hh_W1    = (const float*)d_in[12];
    const float* hh_b1    = (const float*)d_in[13];
    const float* hh_W2    = (const float*)d_in[14];
    const float* hh_b2    = (const float*)d_in[15];
    const float* hop_coef = (const float*)d_in[16];
    float* out = (float*)d_out;

    cudaFuncSetAttribute(mlp_kernel, cudaFuncAttributeMaxDynamicSharedMemorySize, SMEM_BYTES);

    // 152 persistent CTAs (1/SM on GB300), 4 MLP variants; writes d_out base + 3 hop scratches
    mlp_kernel<<<dim3(38, 4), 256, SMEM_BYTES>>>(
        emb, loop_W1, loop_b1, loop_W2, loop_b2,
        rel_W1, rel_b1, rel_W2, rel_b2,
        hh_W1, hh_b1, hh_W2, hh_b2, hop_coef, out);

    // edge scatter-add (depends on mlp_kernel; same stream ordering)
    scatter_kernel<<<1216, 256>>>(ei, ew, out);
}

// round 7
// speedup vs baseline: 1.6981x; 1.6864x over previous
#include <cuda_runtime.h>
#include <cuda_bf16.h>
#include <cstdint>

// Problem constants (fixed by the dataset generator)
#define NN 50000
#define NE 600000
#define CC 128
#define TMR 128                       // tile rows (M)
#define NTL ((NN + TMR - 1) / TMR)    // 391 tiles

#define SROW 136                      // padded row stride in bf16 (272 B; 68 words, 68%32==4)
#define TILE_B (128 * SROW * 2)       // 34816 bytes per bf16 [128 x 128] tile

// ---- smem byte offsets ----
#define SM_B1    0                    // 128 f32 bias1
#define SM_B2    512                  // 128 f32 (scale*bias2)
#define SM_AH    1024                 // X_hi / H_hi  [m][k]
#define SM_AL    (SM_AH + TILE_B)     // X_lo / H_lo
#define SM_W1H   (SM_AL + TILE_B)     // W1_hi [k][n]
#define SM_W1L   (SM_W1H + TILE_B)
#define SM_W2H   (SM_W1L + TILE_B)
#define SM_W2L   (SM_W2H + TILE_B)
#define SM_TOTAL (SM_W2L + TILE_B)    // 209920 B

// Scratch for the 3 hop-scaled MLP outputs (hop_coef folded in).
__device__ float g_G[3][(size_t)NN * CC];

// ---------------- helpers ----------------
__device__ __forceinline__ uint32_t smem_u32(const void* p) {
    uint32_t a;
    asm("{ .reg .u64 t; cvta.to.shared.u64 t, %1; cvt.u32.u64 %0, t; }" : "=r"(a) : "l"(p));
    return a;
}
__device__ __forceinline__ void ldsm4(uint32_t& r0, uint32_t& r1, uint32_t& r2, uint32_t& r3,
                                      uint32_t addr) {
    asm volatile("ldmatrix.sync.aligned.m8n8.x4.shared.b16 {%0,%1,%2,%3}, [%4];"
                 : "=r"(r0), "=r"(r1), "=r"(r2), "=r"(r3) : "r"(addr));
}
__device__ __forceinline__ void ldsm4t(uint32_t& r0, uint32_t& r1, uint32_t& r2, uint32_t& r3,
                                       uint32_t addr) {
    asm volatile("ldmatrix.sync.aligned.m8n8.x4.trans.shared.b16 {%0,%1,%2,%3}, [%4];"
                 : "=r"(r0), "=r"(r1), "=r"(r2), "=r"(r3) : "r"(addr));
}
__device__ __forceinline__ void mma_bf16(float* c, const uint32_t* a, const uint32_t* b) {
    asm volatile(
        "mma.sync.aligned.m16n8k16.row.col.f32.bf16.bf16.f32 "
        "{%0,%1,%2,%3}, {%4,%5,%6,%7}, {%8,%9}, {%0,%1,%2,%3};"
        : "+f"(c[0]), "+f"(c[1]), "+f"(c[2]), "+f"(c[3])
        : "r"(a[0]), "r"(a[1]), "r"(a[2]), "r"(a[3]), "r"(b[0]), "r"(b[1]));
}

// fp32 -> (bf16 hi, bf16 lo) split of 2 values, packed as bf16x2 words
__device__ __forceinline__ void split2(float x, float y, uint32_t& hi, uint32_t& lo) {
    __nv_bfloat16 hx = __float2bfloat16(x);
    __nv_bfloat16 hy = __float2bfloat16(y);
    __nv_bfloat16 lx = __float2bfloat16(x - __bfloat162float(hx));
    __nv_bfloat16 ly = __float2bfloat16(y - __bfloat162float(hy));
    hi = ((uint32_t)__bfloat16_as_ushort(hy) << 16) | (uint32_t)__bfloat16_as_ushort(hx);
    lo = ((uint32_t)__bfloat16_as_ushort(ly) << 16) | (uint32_t)__bfloat16_as_ushort(lx);
}

// One 128x128x128 bf16 MMA pass: c += A(smem [m][k]) @ B(smem [k][n]).
// Warp computes 32(m) x 64(n); a_off/b_off are per-lane ldmatrix byte offsets.
__device__ __forceinline__ void gemm_step(uint32_t aB, uint32_t bB,
                                          uint32_t a_off, uint32_t b_off,
                                          float (&c)[2][8][4]) {
    #pragma unroll
    for (int kc = 0; kc < 8; ++kc) {
        uint32_t a[2][4];
        ldsm4(a[0][0], a[0][1], a[0][2], a[0][3], aB + a_off + kc * 32);
        ldsm4(a[1][0], a[1][1], a[1][2], a[1][3], aB + a_off + 16 * SROW * 2 + kc * 32);
        uint32_t b[8][2];
        #pragma unroll
        for (int np = 0; np < 4; ++np)
            ldsm4t(b[2 * np][0], b[2 * np][1], b[2 * np + 1][0], b[2 * np + 1][1],
                   bB + b_off + kc * (16 * SROW * 2) + np * 32);
        #pragma unroll
        for (int mf = 0; mf < 2; ++mf)
            #pragma unroll
            for (int nf = 0; nf < 8; ++nf)
                mma_bf16(c[mf][nf], a[mf], b[nf]);
    }
}

// 3-product split-bf16 GEMM: c += Ahi*Whi + Ahi*Wlo + Alo*Whi
__device__ __forceinline__ void gemm3(uint32_t AH, uint32_t AL, uint32_t WH, uint32_t WL,
                                      uint32_t a_off, uint32_t b_off, float (&c)[2][8][4]) {
    #pragma unroll 1
    for (int p = 0; p < 3; ++p) {
        uint32_t aB = (p == 2) ? AL : AH;
        uint32_t bB = (p == 1) ? WL : WH;
        gemm_step(aB, bB, a_off, b_off, c);
    }
}

// Fused 2-layer MLP on mma.sync bf16 (split hi/lo for ~fp32 accuracy):
// out = scale * (relu(X@W1 + b1) @ W2 + b2)
__global__ void __launch_bounds__(256, 1)
mlp_mma_kernel(const float* __restrict__ emb,
               const float* __restrict__ loop_W1, const float* __restrict__ loop_b1,
               const float* __restrict__ loop_W2, const float* __restrict__ loop_b2,
               const float* __restrict__ rel_W1,  const float* __restrict__ rel_b1,
               const float* __restrict__ rel_W2,  const float* __restrict__ rel_b2,
               const float* __restrict__ hh_W1,   const float* __restrict__ hh_b1,
               const float* __restrict__ hh_W2,   const float* __restrict__ hh_b2,
               const float* __restrict__ hop_coef,
               float* __restrict__ d_out)
{
    extern __shared__ char smem[];
    const uint32_t sb = smem_u32(smem);
    const int tid  = threadIdx.x;
    const int lane = tid & 31;
    const int wid  = tid >> 5;
    const int warp_m = wid & 3;   // rows 32*warp_m
    const int warp_n = wid >> 2;  // cols 64*warp_n

    // ---- select MLP variant ----
    const int which = blockIdx.y;
    const float *X, *W1, *b1, *W2, *b2;
    float* out;
    float scale = 1.0f;
    if (which == 0) {        // self/loop MLP -> d_out
        X = emb + 2ll * NN * CC;
        W1 = loop_W1; b1 = loop_b1; W2 = loop_W2; b2 = loop_b2;
        out = d_out;
    } else if (which == 1) { // hop 1 (rel MLP on x_t)
        X = emb + 2ll * NN * CC;
        W1 = rel_W1; b1 = rel_b1; W2 = rel_W2; b2 = rel_b2;
        out = g_G[0]; scale = __ldg(hop_coef + 0);
    } else if (which == 2) { // hop 2 (delayed emb[t-1])
        X = emb + 1ll * NN * CC;
        W1 = hh_W1; b1 = hh_b1; W2 = hh_W2; b2 = hh_b2;
        out = g_G[1]; scale = __ldg(hop_coef + 1);
    } else {                 // hop 3 (delayed emb[t-2])
        X = emb;
        W1 = hh_W1 + CC * CC; b1 = hh_b1 + CC; W2 = hh_W2 + CC * CC; b2 = hh_b2 + CC;
        out = g_G[2]; scale = __ldg(hop_coef + 2);
    }

    // ---- biases ----
    if (tid < CC) {
        ((float*)(smem + SM_B1))[tid] = b1[tid];
        ((float*)(smem + SM_B2))[tid] = scale * b2[tid];
    }

    // ---- weights: smem [k][n] bf16 hi/lo, padded stride (coalesced loads) ----
    {
        const int n4 = tid & 31;        // group of 4 n
        const int kk = tid >> 5;        // 0..7
        #pragma unroll 4
        for (int r = 0; r < 16; ++r) {
            int k = r * 8 + kk;
            float4 v1 = *(const float4*)(W1 + (size_t)k * CC + n4 * 4);
            float4 v2 = *(const float4*)(W2 + (size_t)k * CC + n4 * 4);
            uint32_t h0, l0, h1, l1;
            uint32_t w = (uint32_t)k * (SROW / 2) + n4 * 2;   // 32-bit word index
            split2(v1.x, v1.y, h0, l0); split2(v1.z, v1.w, h1, l1);
            *(uint2*)((uint32_t*)(smem + SM_W1H) + w) = make_uint2(h0, h1);
            *(uint2*)((uint32_t*)(smem + SM_W1L) + w) = make_uint2(l0, l1);
            split2(v2.x, v2.y, h0, l0); split2(v2.z, v2.w, h1, l1);
            *(uint2*)((uint32_t*)(smem + SM_W2H) + w) = make_uint2(h0, h1);
            *(uint2*)((uint32_t*)(smem + SM_W2L) + w) = make_uint2(l0, l1);
        }
    }

    // per-lane ldmatrix byte offsets
    const uint32_t a_off = 2u * ((warp_m * 32 + (lane & 15)) * SROW + (lane >> 4) * 8);
    const uint32_t b_off = 2u * ((lane & 15) * SROW + warp_n * 64 + (lane >> 4) * 8);
    const int g  = lane >> 2;   // group id (row within 8)
    const int tg = lane & 3;    // thread-in-group (col pair)
    const uint32_t AH = sb + SM_AH, AL = sb + SM_AL;

    for (int tile = blockIdx.x; tile < NTL; tile += gridDim.x) {
        const int row0 = tile * TMR;

        // ---- load X tile, split to bf16 hi/lo [m][k] ----
        #pragma unroll 4
        for (int it = 0; it < 16; ++it) {
            int idx = tid + it * 256;    // float4 index 0..4095
            int r   = idx >> 5;          // tile row
            int cq  = idx & 31;          // k-group of 4
            float4 v = (row0 + r < NN)
                     ? ((const float4*)(X + (size_t)(row0 + r) * CC))[cq]
                     : make_float4(0.f, 0.f, 0.f, 0.f);
            uint32_t h0, l0, h1, l1;
            split2(v.x, v.y, h0, l0);
            split2(v.z, v.w, h1, l1);
            uint32_t w = (uint32_t)r * (SROW / 2) + cq * 2;
            *(uint2*)((uint32_t*)(smem + SM_AH) + w) = make_uint2(h0, h1);
            *(uint2*)((uint32_t*)(smem + SM_AL) + w) = make_uint2(l0, l1);
        }
        __syncthreads();

        // ---- layer 1: c = X @ W1 (3-product split) ----
        float c[2][8][4];
        #pragma unroll
        for (int mf = 0; mf < 2; ++mf)
            #pragma unroll
            for (int nf = 0; nf < 8; ++nf)
                { c[mf][nf][0] = 0.f; c[mf][nf][1] = 0.f; c[mf][nf][2] = 0.f; c[mf][nf][3] = 0.f; }
        gemm3(AH, AL, sb + SM_W1H, sb + SM_W1L, a_off, b_off, c);
        __syncthreads();   // all warps done reading A before H overwrite

        // ---- epilogue 1: relu(c + b1) -> split -> H tiles (reuse A bufs) ----
        #pragma unroll
        for (int mf = 0; mf < 2; ++mf) {
            int row = warp_m * 32 + mf * 16 + g;
            #pragma unroll
            for (int nf = 0; nf < 8; ++nf) {
                int col = warp_n * 64 + nf * 8 + 2 * tg;
                float2 bb = *(const float2*)((const float*)(smem + SM_B1) + col);
                float h0 = fmaxf(c[mf][nf][0] + bb.x, 0.f);
                float h1 = fmaxf(c[mf][nf][1] + bb.y, 0.f);
                float h2 = fmaxf(c[mf][nf][2] + bb.x, 0.f);
                float h3 = fmaxf(c[mf][nf][3] + bb.y, 0.f);
                uint32_t hi0, lo0, hi1, lo1;
                split2(h0, h1, hi0, lo0);
                split2(h2, h3, hi1, lo1);
                uint32_t w = (uint32_t)row * (SROW / 2) + warp_n * 32 + nf * 4 + tg;
                ((uint32_t*)(smem + SM_AH))[w] = hi0;
                ((uint32_t*)(smem + SM_AL))[w] = lo0;
                ((uint32_t*)(smem + SM_AH))[w + 8 * (SROW / 2)] = hi1;
                ((uint32_t*)(smem + SM_AL))[w + 8 * (SROW / 2)] = lo1;
            }
        }
        __syncthreads();

        // ---- layer 2: c = H @ W2 ----
        #pragma unroll
        for (int mf = 0; mf < 2; ++mf)
            #pragma unroll
            for (int nf = 0; nf < 8; ++nf)
                { c[mf][nf][0] = 0.f; c[mf][nf][1] = 0.f; c[mf][nf][2] = 0.f; c[mf][nf][3] = 0.f; }
        gemm3(AH, AL, sb + SM_W2H, sb + SM_W2L, a_off, b_off, c);

        // ---- epilogue 2: out = scale*c + (scale*b2) ----
        #pragma unroll
        for (int mf = 0; mf < 2; ++mf) {
            int row = warp_m * 32 + mf * 16 + g;
            int gr0 = row0 + row, gr1 = gr0 + 8;
            #pragma unroll
            for (int nf = 0; nf < 8; ++nf) {
                int col = warp_n * 64 + nf * 8 + 2 * tg;
                float2 bb = *(const float2*)((const float*)(smem + SM_B2) + col);
                if (gr0 < NN) {
                    float2 o;
                    o.x = fmaf(c[mf][nf][0], scale, bb.x);
                    o.y = fmaf(c[mf][nf][1], scale, bb.y);
                    *(float2*)(out + (size_t)gr0 * CC + col) = o;
                }
                if (gr1 < NN) {
                    float2 o;
                    o.x = fmaf(c[mf][nf][2], scale, bb.x);
                    o.y = fmaf(c[mf][nf][3], scale, bb.y);
                    *(float2*)(out + (size_t)gr1 * CC + col) = o;
                }
            }
        }
        __syncthreads();   // before next tile overwrites A
    }
}

// One warp per edge: out[row] += G[w-1][col] (coef already folded into G).
__global__ void scatter_kernel(const int* __restrict__ ei,
                               const int* __restrict__ ew,
                               float* __restrict__ out)
{
    const int lane = threadIdx.x & 31;
    int gw = (blockIdx.x * blockDim.x + threadIdx.x) >> 5;
    const int nw = (gridDim.x * blockDim.x) >> 5;
    for (int e = gw; e < NE; e += nw) {
        int row = ei[e];
        int col = ei[NE + e];
        int w = ew[e] - 1;
        if ((unsigned)w > 2u) continue;
        const float4 v = *(const float4*)(&g_G[w][(size_t)col * CC + 4 * lane]);
        float* dst = out + (size_t)row * CC + 4 * lane;
        asm volatile("red.global.add.v4.f32 [%0], {%1, %2, %3, %4};"
                     :: "l"(dst), "f"(v.x), "f"(v.y), "f"(v.z), "f"(v.w)
                     : "memory");
    }
}

extern "C" void kernel_launch(void* const* d_in, const int* in_sizes, int n_in,
                              void* d_out, int out_size) {
    const float* emb      = (const float*)d_in[1];
    const int*   ei       = (const int*)  d_in[2];
    const int*   ew       = (const int*)  d_in[3];
    const float* loop_W1  = (const float*)d_in[4];
    const float* loop_b1  = (const float*)d_in[5];
    const float* loop_W2  = (const float*)d_in[6];
    const float* loop_b2  = (const float*)d_in[7];
    const float* rel_W1   = (const float*)d_in[8];
    const float* rel_b1   = (const float*)d_in[9];
    const float* rel_W2   = (const float*)d_in[10];
    const float* rel_b2   = (const float*)d_in[11];
    const float* hh_W1    = (const float*)d_in[12];
    const float* hh_b1    = (const float*)d_in[13];
    const float* hh_W2    = (const float*)d_in[14];
    const float* hh_b2    = (const float*)d_in[15];
    const float* hop_coef = (const float*)d_in[16];
    float* out = (float*)d_out;

    cudaFuncSetAttribute(mlp_mma_kernel, cudaFuncAttributeMaxDynamicSharedMemorySize, SM_TOTAL);

    // 148 CTAs (1/SM), 4 MLP variants x 37 tile-strides
    mlp_mma_kernel<<<dim3(37, 4), 256, SM_TOTAL>>>(
        emb, loop_W1, loop_b1, loop_W2, loop_b2,
        rel_W1, rel_b1, rel_W2, rel_b2,
        hh_W1, hh_b1, hh_W2, hh_b2, hop_coef, out);

    scatter_kernel<<<1216, 256>>>(ei, ew, out);
}